// round 5
// baseline (speedup 1.0000x reference)
#include <cuda_runtime.h>
#include <cuda_bf16.h>
#include <math.h>

// Problem constants
#define BATCH 2
#define SEQ   2048
#define DM    1024
#define NH    16
#define DH    64
#define DFF   512
#define ROWS  (BATCH*SEQ)          // 4096

// ---------------- scratch (device globals; no runtime allocation) ----------
__device__ float g_xn[ROWS*DM];    // norm1(x)
__device__ float g_q [ROWS*DM];
__device__ float g_k [ROWS*DM];
__device__ float g_v [ROWS*DM];
__device__ float g_ao[ROWS*DM];    // attention output (pre-Wo)
__device__ float g_x2[ROWS*DM];    // x_n + attn@Wo + bo
__device__ float g_hn[ROWS*DM];    // norm2(x2)
__device__ float g_h1[ROWS*DFF];   // relu(hn@W1+b1)

// ---------------- NormLayer: alpha*(x-mean)/sqrt(var_unbiased+eps)+beta ----
__global__ __launch_bounds__(256)
void norm_kernel(const float* __restrict__ X,
                 const float* __restrict__ alpha,
                 const float* __restrict__ beta,
                 float* __restrict__ Y)
{
    int row = blockIdx.x;
    int tid = threadIdx.x;
    const float* xr = X + (size_t)row * DM;

    float4 v = *(const float4*)(xr + tid * 4);
    float s  = v.x + v.y + v.z + v.w;
    float sq = v.x*v.x + v.y*v.y + v.z*v.z + v.w*v.w;

    // warp reduce
    #pragma unroll
    for (int m = 16; m; m >>= 1) {
        s  += __shfl_xor_sync(0xffffffffu, s,  m);
        sq += __shfl_xor_sync(0xffffffffu, sq, m);
    }
    __shared__ float red[16];
    __shared__ float s_mean, s_rstd;
    int wid  = tid >> 5;
    int lane = tid & 31;
    if (lane == 0) { red[wid] = s; red[8 + wid] = sq; }
    __syncthreads();
    if (tid == 0) {
        float S = 0.f, SQ = 0.f;
        #pragma unroll
        for (int w = 0; w < 8; w++) { S += red[w]; SQ += red[8 + w]; }
        float mean = S * (1.0f / DM);
        float var  = (SQ - (float)DM * mean * mean) * (1.0f / (DM - 1));
        s_mean = mean;
        s_rstd = rsqrtf(var + 1e-6f);
    }
    __syncthreads();
    float mean = s_mean, rstd = s_rstd;

    float4 a = *(const float4*)(alpha + tid * 4);
    float4 b = *(const float4*)(beta  + tid * 4);
    float4 o;
    o.x = a.x * (v.x - mean) * rstd + b.x;
    o.y = a.y * (v.y - mean) * rstd + b.y;
    o.z = a.z * (v.z - mean) * rstd + b.z;
    o.w = a.w * (v.w - mean) * rstd + b.w;
    *(float4*)(Y + (size_t)row * DM + tid * 4) = o;
}

// ---------------- SGEMM: C = [Res +] act(A@B + bias) -----------------------
// A: [M,K] row-major, B: [K,N] row-major. Tiles 128x128x8, 256 threads,
// 8x8 micro-tile, double-buffered smem. All dims assumed divisible.
template<bool RELU, bool HAS_RES>
__global__ __launch_bounds__(256, 2)
void sgemm128(const float* __restrict__ A, const float* __restrict__ B,
              const float* __restrict__ bias, const float* __restrict__ Res,
              float* __restrict__ C, int M, int N, int K)
{
    __shared__ float As[2][8 * 128];
    __shared__ float Bs[2][8 * 128];

    int tid = threadIdx.x;
    int bm = blockIdx.y, bn = blockIdx.x;

    // A tile loader: row = tid/2 (0..127), k offset = (tid&1)*4
    int a_row = tid >> 1;
    int a_c4  = (tid & 1) << 2;
    const float* Aptr = A + (size_t)(bm * 128 + a_row) * K + a_c4;

    // B tile loader: k = tid/32 (0..7), col = (tid&31)*4
    int b_k = tid >> 5;
    int b_c = (tid & 31) << 2;
    const float* Bptr = B + (size_t)b_k * N + bn * 128 + b_c;

    int nk = K >> 3;

    float4 av = *(const float4*)Aptr;
    float4 bv = *(const float4*)Bptr;
    As[0][(a_c4 + 0) * 128 + a_row] = av.x;
    As[0][(a_c4 + 1) * 128 + a_row] = av.y;
    As[0][(a_c4 + 2) * 128 + a_row] = av.z;
    As[0][(a_c4 + 3) * 128 + a_row] = av.w;
    *(float4*)&Bs[0][b_k * 128 + b_c] = bv;
    __syncthreads();

    float acc[8][8];
    #pragma unroll
    for (int i = 0; i < 8; i++)
        #pragma unroll
        for (int j = 0; j < 8; j++) acc[i][j] = 0.f;

    int tm = (tid >> 4) << 3;   // 0..120
    int tn = (tid & 15) << 3;   // 0..120

    int cur = 0;
    for (int kt = 0; kt < nk; kt++) {
        bool has_next = (kt + 1 < nk);
        if (has_next) {
            av = *(const float4*)(Aptr + (kt + 1) * 8);
            bv = *(const float4*)(Bptr + (size_t)(kt + 1) * 8 * N);
        }
        #pragma unroll
        for (int kk = 0; kk < 8; kk++) {
            float4 a0 = *(float4*)&As[cur][kk * 128 + tm];
            float4 a1 = *(float4*)&As[cur][kk * 128 + tm + 4];
            float4 b0 = *(float4*)&Bs[cur][kk * 128 + tn];
            float4 b1 = *(float4*)&Bs[cur][kk * 128 + tn + 4];
            float a[8] = {a0.x, a0.y, a0.z, a0.w, a1.x, a1.y, a1.z, a1.w};
            float b[8] = {b0.x, b0.y, b0.z, b0.w, b1.x, b1.y, b1.z, b1.w};
            #pragma unroll
            for (int i = 0; i < 8; i++)
                #pragma unroll
                for (int j = 0; j < 8; j++)
                    acc[i][j] += a[i] * b[j];
        }
        if (has_next) {
            int nxt = cur ^ 1;
            As[nxt][(a_c4 + 0) * 128 + a_row] = av.x;
            As[nxt][(a_c4 + 1) * 128 + a_row] = av.y;
            As[nxt][(a_c4 + 2) * 128 + a_row] = av.z;
            As[nxt][(a_c4 + 3) * 128 + a_row] = av.w;
            *(float4*)&Bs[nxt][b_k * 128 + b_c] = bv;
            __syncthreads();
            cur = nxt;
        }
    }

    // epilogue
    int gn0 = bn * 128 + tn;
    float4 bias0 = *(const float4*)(bias + gn0);
    float4 bias1 = *(const float4*)(bias + gn0 + 4);
    #pragma unroll
    for (int i = 0; i < 8; i++) {
        size_t gm = (size_t)(bm * 128 + tm + i);
        float* cp = C + gm * N + gn0;
        float4 c0, c1;
        c0.x = acc[i][0] + bias0.x; c0.y = acc[i][1] + bias0.y;
        c0.z = acc[i][2] + bias0.z; c0.w = acc[i][3] + bias0.w;
        c1.x = acc[i][4] + bias1.x; c1.y = acc[i][5] + bias1.y;
        c1.z = acc[i][6] + bias1.z; c1.w = acc[i][7] + bias1.w;
        if (RELU) {
            c0.x = fmaxf(c0.x, 0.f); c0.y = fmaxf(c0.y, 0.f);
            c0.z = fmaxf(c0.z, 0.f); c0.w = fmaxf(c0.w, 0.f);
            c1.x = fmaxf(c1.x, 0.f); c1.y = fmaxf(c1.y, 0.f);
            c1.z = fmaxf(c1.z, 0.f); c1.w = fmaxf(c1.w, 0.f);
        }
        if (HAS_RES) {
            const float* rp = Res + gm * N + gn0;
            float4 r0 = *(const float4*)rp;
            float4 r1 = *(const float4*)(rp + 4);
            c0.x += r0.x; c0.y += r0.y; c0.z += r0.z; c0.w += r0.w;
            c1.x += r1.x; c1.y += r1.y; c1.z += r1.z; c1.w += r1.w;
        }
        *(float4*)cp       = c0;
        *(float4*)(cp + 4) = c1;
    }
}

// ---------------- Flash attention: per (b,h), 64-query tiles ---------------
// Q/K/V are [ROWS, DM] with head h occupying cols [h*64, h*64+64).
// Block: 256 threads (16x16), each thread owns a 4x4 patch of the 64x64
// score tile and a 4x4 patch of the 64x64 output tile.
#define ATT_STRIDE 65
__global__ __launch_bounds__(256)
void attn_kernel(const float* __restrict__ Q, const float* __restrict__ Kb,
                 const float* __restrict__ Vb, float* __restrict__ O)
{
    extern __shared__ float sm[];
    float* sQ = sm;                        // 64*65
    float* sK = sm + 64 * ATT_STRIDE;      // aliased as P after scores
    float* sV = sm + 2 * 64 * ATT_STRIDE;

    int tid = threadIdx.x;
    int bh = blockIdx.y;
    int b = bh >> 4, h = bh & 15;
    int q0 = blockIdx.x * 64;
    size_t base = (size_t)b * SEQ * DM + h * DH;

    // load Q tile (64 rows x 64 cols)
    for (int t = tid; t < 64 * 16; t += 256) {
        int r = t >> 4, c4 = (t & 15) << 2;
        float4 v = *(const float4*)(Q + base + (size_t)(q0 + r) * DM + c4);
        float* d = &sQ[r * ATT_STRIDE + c4];
        d[0] = v.x; d[1] = v.y; d[2] = v.z; d[3] = v.w;
    }

    int ty = tid >> 4, tx = tid & 15;
    int r0 = ty * 4, c0 = tx * 4;

    float m_i[4], l_i[4], o_acc[4][4];
    #pragma unroll
    for (int i = 0; i < 4; i++) {
        m_i[i] = -INFINITY; l_i[i] = 0.f;
        #pragma unroll
        for (int j = 0; j < 4; j++) o_acc[i][j] = 0.f;
    }
    __syncthreads();

    const float scale = 0.125f;   // 1/sqrt(64)

    for (int kt = 0; kt < SEQ / 64; kt++) {
        int k0 = kt * 64;
        // load K and V tiles
        for (int t = tid; t < 64 * 16; t += 256) {
            int r = t >> 4, c4 = (t & 15) << 2;
            size_t goff = base + (size_t)(k0 + r) * DM + c4;
            float4 kv = *(const float4*)(Kb + goff);
            float4 vv = *(const float4*)(Vb + goff);
            float* dk = &sK[r * ATT_STRIDE + c4];
            dk[0] = kv.x; dk[1] = kv.y; dk[2] = kv.z; dk[3] = kv.w;
            float* dv = &sV[r * ATT_STRIDE + c4];
            dv[0] = vv.x; dv[1] = vv.y; dv[2] = vv.z; dv[3] = vv.w;
        }
        __syncthreads();

        // scores s[i][j] = (Q[r0+i] . K[c0+j]) * scale
        float s[4][4];
        #pragma unroll
        for (int i = 0; i < 4; i++)
            #pragma unroll
            for (int j = 0; j < 4; j++) s[i][j] = 0.f;

        #pragma unroll 4
        for (int kk = 0; kk < 64; kk++) {
            float qv[4], kv[4];
            #pragma unroll
            for (int i = 0; i < 4; i++) qv[i] = sQ[(r0 + i) * ATT_STRIDE + kk];
            #pragma unroll
            for (int j = 0; j < 4; j++) kv[j] = sK[(c0 + j) * ATT_STRIDE + kk];
            #pragma unroll
            for (int i = 0; i < 4; i++)
                #pragma unroll
                for (int j = 0; j < 4; j++)
                    s[i][j] += qv[i] * kv[j];
        }
        __syncthreads();   // done reading sK; may be overwritten by P

        // online softmax update per row
        #pragma unroll
        for (int i = 0; i < 4; i++) {
            float mx = -INFINITY;
            #pragma unroll
            for (int j = 0; j < 4; j++) {
                s[i][j] *= scale;
                mx = fmaxf(mx, s[i][j]);
            }
            #pragma unroll
            for (int m = 8; m; m >>= 1)
                mx = fmaxf(mx, __shfl_xor_sync(0xffffffffu, mx, m));
            float mnew  = fmaxf(m_i[i], mx);
            float alpha = __expf(m_i[i] - mnew);
            float psum = 0.f;
            #pragma unroll
            for (int j = 0; j < 4; j++) {
                float p = __expf(s[i][j] - mnew);
                s[i][j] = p;
                psum += p;
            }
            #pragma unroll
            for (int m = 8; m; m >>= 1)
                psum += __shfl_xor_sync(0xffffffffu, psum, m);
            l_i[i] = l_i[i] * alpha + psum;
            m_i[i] = mnew;
            #pragma unroll
            for (int j = 0; j < 4; j++) o_acc[i][j] *= alpha;
        }

        // write P into sK alias
        #pragma unroll
        for (int i = 0; i < 4; i++)
            #pragma unroll
            for (int j = 0; j < 4; j++)
                sK[(r0 + i) * ATT_STRIDE + (c0 + j)] = s[i][j];
        __syncthreads();

        // O += P @ V
        #pragma unroll 4
        for (int c = 0; c < 64; c++) {
            float pv[4], vv[4];
            #pragma unroll
            for (int i = 0; i < 4; i++) pv[i] = sK[(r0 + i) * ATT_STRIDE + c];
            #pragma unroll
            for (int j = 0; j < 4; j++) vv[j] = sV[c * ATT_STRIDE + (c0 + j)];
            #pragma unroll
            for (int i = 0; i < 4; i++)
                #pragma unroll
                for (int j = 0; j < 4; j++)
                    o_acc[i][j] += pv[i] * vv[j];
        }
        __syncthreads();
    }

    // write normalized output
    #pragma unroll
    for (int i = 0; i < 4; i++) {
        float inv = 1.0f / l_i[i];
        #pragma unroll
        for (int j = 0; j < 4; j++)
            O[base + (size_t)(q0 + r0 + i) * DM + (c0 + j)] = o_acc[i][j] * inv;
    }
}

// ---------------- launcher -------------------------------------------------
extern "C" void kernel_launch(void* const* d_in, const int* in_sizes, int n_in,
                              void* d_out, int out_size)
{
    const float* x      = (const float*)d_in[0];
    const float* Wq     = (const float*)d_in[1];
    const float* bq     = (const float*)d_in[2];
    const float* Wk     = (const float*)d_in[3];
    const float* bk     = (const float*)d_in[4];
    const float* Wv     = (const float*)d_in[5];
    const float* bv     = (const float*)d_in[6];
    const float* Wo     = (const float*)d_in[7];
    const float* bo     = (const float*)d_in[8];
    const float* alpha1 = (const float*)d_in[9];
    const float* beta1  = (const float*)d_in[10];
    const float* alpha2 = (const float*)d_in[11];
    const float* beta2  = (const float*)d_in[12];
    const float* W1     = (const float*)d_in[13];
    const float* b1     = (const float*)d_in[14];
    const float* W2     = (const float*)d_in[15];
    const float* b2     = (const float*)d_in[16];
    float* out = (float*)d_out;

    float *xn, *q, *k, *v, *ao, *x2, *hn, *h1;
    cudaGetSymbolAddress((void**)&xn, g_xn);
    cudaGetSymbolAddress((void**)&q,  g_q);
    cudaGetSymbolAddress((void**)&k,  g_k);
    cudaGetSymbolAddress((void**)&v,  g_v);
    cudaGetSymbolAddress((void**)&ao, g_ao);
    cudaGetSymbolAddress((void**)&x2, g_x2);
    cudaGetSymbolAddress((void**)&hn, g_hn);
    cudaGetSymbolAddress((void**)&h1, g_h1);

    // 1. x_n = norm1(x)
    norm_kernel<<<ROWS, 256>>>(x, alpha1, beta1, xn);

    // 2. Q/K/V projections
    dim3 gqkv(DM / 128, ROWS / 128);   // (8, 32)
    sgemm128<false, false><<<gqkv, 256>>>(xn, Wq, bq, nullptr, q,  ROWS, DM, DM);
    sgemm128<false, false><<<gqkv, 256>>>(xn, Wk, bk, nullptr, k,  ROWS, DM, DM);
    sgemm128<false, false><<<gqkv, 256>>>(xn, Wv, bv, nullptr, v,  ROWS, DM, DM);

    // 3. attention
    int att_smem = 3 * 64 * ATT_STRIDE * (int)sizeof(float);   // 49920 B
    cudaFuncSetAttribute(attn_kernel, cudaFuncAttributeMaxDynamicSharedMemorySize, att_smem);
    attn_kernel<<<dim3(SEQ / 64, BATCH * NH), 256, att_smem>>>(q, k, v, ao);

    // 4. x2 = x_n + ao@Wo + bo
    sgemm128<false, true><<<gqkv, 256>>>(ao, Wo, bo, xn, x2, ROWS, DM, DM);

    // 5. h_n = norm2(x2)
    norm_kernel<<<ROWS, 256>>>(x2, alpha2, beta2, hn);

    // 6. h1 = relu(h_n@W1 + b1)
    sgemm128<true, false><<<dim3(DFF / 128, ROWS / 128), 256>>>(hn, W1, b1, nullptr, h1, ROWS, DFF, DM);

    // 7. out = x2 + h1@W2 + b2
    sgemm128<false, true><<<dim3(DM / 128, ROWS / 128), 256>>>(h1, W2, b2, x2, out, ROWS, DM, DFF);
}

// round 6
// speedup vs baseline: 3.3838x; 3.3838x over previous
#include <cuda_runtime.h>
#include <cuda_bf16.h>
#include <math.h>
#include <stdint.h>

// Problem constants
#define BATCH 2
#define SEQ   2048
#define DM    1024
#define NH    16
#define DH    64
#define DFF   512
#define ROWS  (BATCH*SEQ)          // 4096

// ---------------- scratch (device globals; no runtime allocation) ----------
__device__ float g_xn[ROWS*DM];    // norm1(x)
__device__ float g_q [ROWS*DM];
__device__ float g_k [ROWS*DM];
__device__ float g_v [ROWS*DM];
__device__ float g_ao[ROWS*DM];    // attention output (pre-Wo)
__device__ float g_x2[ROWS*DM];    // x_n + attn@Wo + bo
__device__ float g_hn[ROWS*DM];    // norm2(x2)
__device__ float g_h1[ROWS*DFF];   // relu(hn@W1+b1)

// ---------------- helpers ---------------------------------------------------
__device__ __forceinline__ float to_tf32(float x) {
    float r;
    asm("cvt.rna.tf32.f32 %0, %1;" : "=f"(r) : "f"(x));
    return r;
}

__device__ __forceinline__ void mma_tf32(float c[4],
                                         uint32_t a0, uint32_t a1, uint32_t a2, uint32_t a3,
                                         uint32_t b0, uint32_t b1) {
    asm volatile(
        "mma.sync.aligned.m16n8k8.row.col.f32.tf32.tf32.f32 "
        "{%0,%1,%2,%3}, {%4,%5,%6,%7}, {%8,%9}, {%0,%1,%2,%3};"
        : "+f"(c[0]), "+f"(c[1]), "+f"(c[2]), "+f"(c[3])
        : "r"(a0), "r"(a1), "r"(a2), "r"(a3), "r"(b0), "r"(b1));
}

// ---------------- NormLayer: alpha*(x-mean)/sqrt(var_unbiased+eps)+beta ----
__global__ __launch_bounds__(256)
void norm_kernel(const float* __restrict__ X,
                 const float* __restrict__ alpha,
                 const float* __restrict__ beta,
                 float* __restrict__ Y)
{
    int row = blockIdx.x;
    int tid = threadIdx.x;
    const float* xr = X + (size_t)row * DM;

    float4 v = *(const float4*)(xr + tid * 4);
    float s  = v.x + v.y + v.z + v.w;
    float sq = v.x*v.x + v.y*v.y + v.z*v.z + v.w*v.w;

    #pragma unroll
    for (int m = 16; m; m >>= 1) {
        s  += __shfl_xor_sync(0xffffffffu, s,  m);
        sq += __shfl_xor_sync(0xffffffffu, sq, m);
    }
    __shared__ float red[16];
    __shared__ float s_mean, s_rstd;
    int wid  = tid >> 5;
    int lane = tid & 31;
    if (lane == 0) { red[wid] = s; red[8 + wid] = sq; }
    __syncthreads();
    if (tid == 0) {
        float S = 0.f, SQ = 0.f;
        #pragma unroll
        for (int w = 0; w < 8; w++) { S += red[w]; SQ += red[8 + w]; }
        float mean = S * (1.0f / DM);
        float var  = (SQ - (float)DM * mean * mean) * (1.0f / (DM - 1));
        s_mean = mean;
        s_rstd = rsqrtf(var + 1e-6f);
    }
    __syncthreads();
    float mean = s_mean, rstd = s_rstd;

    float4 a = *(const float4*)(alpha + tid * 4);
    float4 b = *(const float4*)(beta  + tid * 4);
    float4 o;
    o.x = a.x * (v.x - mean) * rstd + b.x;
    o.y = a.y * (v.y - mean) * rstd + b.y;
    o.z = a.z * (v.z - mean) * rstd + b.z;
    o.w = a.w * (v.w - mean) * rstd + b.w;
    *(float4*)(Y + (size_t)row * DM + tid * 4) = o;
}

// ---------------- tf32 tensor-core GEMM: C = [Res +] act(A@B + bias) -------
// A: [M,K] row-major, B: [K,N] row-major. Block tile 128x128, k-chunk 16.
// 8 warps (2 m x 4 n), warp tile 64x32 = 4x4 m16n8k8 tiles.
// smem: A in [m][k] stride 20 (conflict-free A-frag loads),
//       B in [k][n] stride 136 (conflict-free B-frag loads).
#define SA_STR 20
#define SB_STR 136
template<bool RELU, bool HAS_RES>
__global__ __launch_bounds__(256)
void tgemm(const float* __restrict__ A, const float* __restrict__ B,
           const float* __restrict__ bias, const float* __restrict__ Res,
           float* __restrict__ C, int M, int N, int K)
{
    __shared__ float sA[2][128 * SA_STR];
    __shared__ float sB[2][16 * SB_STR];

    int tid  = threadIdx.x;
    int warp = tid >> 5, lane = tid & 31;
    int gid  = lane >> 2, tg = lane & 3;
    int wm   = (warp & 1) * 64;
    int wn   = (warp >> 1) * 32;
    int bm = blockIdx.y, bn = blockIdx.x;

    // loader indices
    int am[2], ac4[2], bk[2], bn4[2];
    #pragma unroll
    for (int i = 0; i < 2; i++) {
        int f = tid + 256 * i;
        am[i]  = f >> 2;            // 0..127
        ac4[i] = (f & 3) << 2;      // 0,4,8,12
        bk[i]  = f >> 5;            // 0..15
        bn4[i] = (f & 31) << 2;     // 0..124
    }
    const float* Abase = A + (size_t)(bm * 128) * K;
    const float* Bbase = B + bn * 128;

    int nk = K >> 4;

    // prologue: chunk 0 -> buf 0
    #pragma unroll
    for (int i = 0; i < 2; i++) {
        float4 va = *(const float4*)(Abase + (size_t)am[i] * K + ac4[i]);
        va.x = to_tf32(va.x); va.y = to_tf32(va.y);
        va.z = to_tf32(va.z); va.w = to_tf32(va.w);
        *(float4*)&sA[0][am[i] * SA_STR + ac4[i]] = va;
        float4 vb = *(const float4*)(Bbase + (size_t)bk[i] * N + bn4[i]);
        vb.x = to_tf32(vb.x); vb.y = to_tf32(vb.y);
        vb.z = to_tf32(vb.z); vb.w = to_tf32(vb.w);
        *(float4*)&sB[0][bk[i] * SB_STR + bn4[i]] = vb;
    }
    __syncthreads();

    float acc[4][4][4];
    #pragma unroll
    for (int mt = 0; mt < 4; mt++)
        #pragma unroll
        for (int nt = 0; nt < 4; nt++)
            #pragma unroll
            for (int r = 0; r < 4; r++) acc[mt][nt][r] = 0.f;

    int cur = 0;
    for (int kt = 0; kt < nk; kt++) {
        float4 va[2], vb[2];
        bool has_next = (kt + 1 < nk);
        if (has_next) {
            int k0 = (kt + 1) << 4;
            #pragma unroll
            for (int i = 0; i < 2; i++) {
                va[i] = *(const float4*)(Abase + (size_t)am[i] * K + k0 + ac4[i]);
                vb[i] = *(const float4*)(Bbase + (size_t)(k0 + bk[i]) * N + bn4[i]);
            }
        }

        const float* As = sA[cur];
        const float* Bs = sB[cur];
        #pragma unroll
        for (int kk = 0; kk < 16; kk += 8) {
            uint32_t af[4][4], bf[4][2];
            #pragma unroll
            for (int mt = 0; mt < 4; mt++) {
                int r0 = (wm + mt * 16 + gid) * SA_STR;
                int r1 = (wm + mt * 16 + gid + 8) * SA_STR;
                af[mt][0] = __float_as_uint(As[r0 + kk + tg]);
                af[mt][1] = __float_as_uint(As[r1 + kk + tg]);
                af[mt][2] = __float_as_uint(As[r0 + kk + tg + 4]);
                af[mt][3] = __float_as_uint(As[r1 + kk + tg + 4]);
            }
            #pragma unroll
            for (int nt = 0; nt < 4; nt++) {
                int cc = wn + nt * 8 + gid;
                bf[nt][0] = __float_as_uint(Bs[(kk + tg) * SB_STR + cc]);
                bf[nt][1] = __float_as_uint(Bs[(kk + tg + 4) * SB_STR + cc]);
            }
            #pragma unroll
            for (int mt = 0; mt < 4; mt++)
                #pragma unroll
                for (int nt = 0; nt < 4; nt++)
                    mma_tf32(acc[mt][nt], af[mt][0], af[mt][1], af[mt][2], af[mt][3],
                             bf[nt][0], bf[nt][1]);
        }

        if (has_next) {
            int nxt = cur ^ 1;
            #pragma unroll
            for (int i = 0; i < 2; i++) {
                va[i].x = to_tf32(va[i].x); va[i].y = to_tf32(va[i].y);
                va[i].z = to_tf32(va[i].z); va[i].w = to_tf32(va[i].w);
                *(float4*)&sA[nxt][am[i] * SA_STR + ac4[i]] = va[i];
                vb[i].x = to_tf32(vb[i].x); vb[i].y = to_tf32(vb[i].y);
                vb[i].z = to_tf32(vb[i].z); vb[i].w = to_tf32(vb[i].w);
                *(float4*)&sB[nxt][bk[i] * SB_STR + bn4[i]] = vb[i];
            }
            __syncthreads();
            cur = nxt;
        }
    }

    // epilogue
    #pragma unroll
    for (int nt = 0; nt < 4; nt++) {
        int col = bn * 128 + wn + nt * 8 + 2 * tg;
        float2 bv = *(const float2*)(bias + col);
        #pragma unroll
        for (int mt = 0; mt < 4; mt++) {
            int r0 = bm * 128 + wm + mt * 16 + gid;
            int r1 = r0 + 8;
            float2 c0 = make_float2(acc[mt][nt][0] + bv.x, acc[mt][nt][1] + bv.y);
            float2 c1 = make_float2(acc[mt][nt][2] + bv.x, acc[mt][nt][3] + bv.y);
            if (RELU) {
                c0.x = fmaxf(c0.x, 0.f); c0.y = fmaxf(c0.y, 0.f);
                c1.x = fmaxf(c1.x, 0.f); c1.y = fmaxf(c1.y, 0.f);
            }
            if (HAS_RES) {
                float2 r0v = *(const float2*)(Res + (size_t)r0 * N + col);
                float2 r1v = *(const float2*)(Res + (size_t)r1 * N + col);
                c0.x += r0v.x; c0.y += r0v.y;
                c1.x += r1v.x; c1.y += r1v.y;
            }
            *(float2*)(C + (size_t)r0 * N + col) = c0;
            *(float2*)(C + (size_t)r1 * N + col) = c1;
        }
    }
}

// ---------------- tf32 mma flash attention ---------------------------------
// Block: 128 threads (4 warps), 64 queries x dh=64. K/V streamed in 64-key
// tiles. Q fragments live in registers for the whole pass. S = Q@K^T via mma
// (K transposed in smem), online softmax, P round-trips through smem as tf32,
// O += P@V via mma.
#define AT_STR 72
__global__ __launch_bounds__(128)
void attn_mma_kernel(const float* __restrict__ Q, const float* __restrict__ Kb,
                     const float* __restrict__ Vb, float* __restrict__ O)
{
    extern __shared__ float sm[];
    float* sKT = sm;                    // [d=64][key=64+pad]  (K transposed)
    float* sV  = sm + 64 * AT_STR;      // [key=64][d=64+pad]
    float* sP  = sm + 2 * 64 * AT_STR;  // temp (Q load, K load) then P [q][key]

    int tid  = threadIdx.x;
    int warp = tid >> 5, lane = tid & 31;
    int gid  = lane >> 2, tg = lane & 3;
    int wq   = warp * 16;

    int b = blockIdx.y >> 4, h = blockIdx.y & 15;
    int q0 = blockIdx.x * 64;
    size_t base = (size_t)b * SEQ * DM + h * DH;

    // ---- load Q tile into sP temp [q][AT_STR], then fragments to registers
    for (int f = tid; f < 64 * 16; f += 128) {
        int q = f >> 4, c4 = (f & 15) << 2;
        float4 v = *(const float4*)(Q + base + (size_t)(q0 + q) * DM + c4);
        v.x = to_tf32(v.x); v.y = to_tf32(v.y);
        v.z = to_tf32(v.z); v.w = to_tf32(v.w);
        *(float4*)&sP[q * AT_STR + c4] = v;
    }
    __syncthreads();

    uint32_t qf[8][4];
    #pragma unroll
    for (int ks = 0; ks < 8; ks++) {
        int k = ks * 8;
        int r0 = (wq + gid) * AT_STR, r1 = (wq + gid + 8) * AT_STR;
        qf[ks][0] = __float_as_uint(sP[r0 + k + tg]);
        qf[ks][1] = __float_as_uint(sP[r1 + k + tg]);
        qf[ks][2] = __float_as_uint(sP[r0 + k + tg + 4]);
        qf[ks][3] = __float_as_uint(sP[r1 + k + tg + 4]);
    }
    __syncthreads();

    float o[8][4];
    #pragma unroll
    for (int nt = 0; nt < 8; nt++)
        #pragma unroll
        for (int r = 0; r < 4; r++) o[nt][r] = 0.f;
    float m_lo = -INFINITY, m_hi = -INFINITY, l_lo = 0.f, l_hi = 0.f;

    // transpose mapping (conflict-free writes)
    int key8 = tid & 7, d4g = (tid >> 3) & 3, rep = tid >> 5;

    const float scale = 0.125f;   // 1/sqrt(64)

    for (int kt = 0; kt < SEQ / 64; kt++) {
        int k0 = kt * 64;
        // ---- load K (to sP temp) and V tiles, tf32-converted
        for (int f = tid; f < 64 * 16; f += 128) {
            int key = f >> 4, c4 = (f & 15) << 2;
            size_t goff = base + (size_t)(k0 + key) * DM + c4;
            float4 kv = *(const float4*)(Kb + goff);
            kv.x = to_tf32(kv.x); kv.y = to_tf32(kv.y);
            kv.z = to_tf32(kv.z); kv.w = to_tf32(kv.w);
            *(float4*)&sP[key * AT_STR + c4] = kv;
            float4 vv = *(const float4*)(Vb + goff);
            vv.x = to_tf32(vv.x); vv.y = to_tf32(vv.y);
            vv.z = to_tf32(vv.z); vv.w = to_tf32(vv.w);
            *(float4*)&sV[key * AT_STR + c4] = vv;
        }
        __syncthreads();

        // ---- transpose sP[key][d] -> sKT[d][key]
        #pragma unroll
        for (int kk2 = 0; kk2 < 2; kk2++) {
            int key = (rep * 2 + kk2) * 8 + key8;
            #pragma unroll
            for (int j = 0; j < 16; j++) {
                int d = d4g + 4 * j;
                sKT[d * AT_STR + key] = sP[key * AT_STR + d];
            }
        }
        __syncthreads();

        // ---- S = Q @ K^T  (warp: 16 q rows x 64 keys)
        float s[8][4];
        #pragma unroll
        for (int nt = 0; nt < 8; nt++)
            #pragma unroll
            for (int r = 0; r < 4; r++) s[nt][r] = 0.f;

        #pragma unroll
        for (int ks = 0; ks < 8; ks++) {
            uint32_t bf[8][2];
            int kr0 = (ks * 8 + tg) * AT_STR;
            int kr1 = (ks * 8 + tg + 4) * AT_STR;
            #pragma unroll
            for (int nt = 0; nt < 8; nt++) {
                int cc = nt * 8 + gid;
                bf[nt][0] = __float_as_uint(sKT[kr0 + cc]);
                bf[nt][1] = __float_as_uint(sKT[kr1 + cc]);
            }
            #pragma unroll
            for (int nt = 0; nt < 8; nt++)
                mma_tf32(s[nt], qf[ks][0], qf[ks][1], qf[ks][2], qf[ks][3],
                         bf[nt][0], bf[nt][1]);
        }

        // ---- online softmax (rows: q_lo = wq+gid, q_hi = wq+gid+8)
        float mx_lo = -INFINITY, mx_hi = -INFINITY;
        #pragma unroll
        for (int nt = 0; nt < 8; nt++) {
            s[nt][0] *= scale; s[nt][1] *= scale;
            s[nt][2] *= scale; s[nt][3] *= scale;
            mx_lo = fmaxf(mx_lo, fmaxf(s[nt][0], s[nt][1]));
            mx_hi = fmaxf(mx_hi, fmaxf(s[nt][2], s[nt][3]));
        }
        #pragma unroll
        for (int off = 1; off < 4; off <<= 1) {
            mx_lo = fmaxf(mx_lo, __shfl_xor_sync(0xffffffffu, mx_lo, off));
            mx_hi = fmaxf(mx_hi, __shfl_xor_sync(0xffffffffu, mx_hi, off));
        }
        float mn_lo = fmaxf(m_lo, mx_lo);
        float mn_hi = fmaxf(m_hi, mx_hi);
        float al_lo = __expf(m_lo - mn_lo);
        float al_hi = __expf(m_hi - mn_hi);
        float ps_lo = 0.f, ps_hi = 0.f;
        #pragma unroll
        for (int nt = 0; nt < 8; nt++) {
            s[nt][0] = __expf(s[nt][0] - mn_lo);
            s[nt][1] = __expf(s[nt][1] - mn_lo);
            s[nt][2] = __expf(s[nt][2] - mn_hi);
            s[nt][3] = __expf(s[nt][3] - mn_hi);
            ps_lo += s[nt][0] + s[nt][1];
            ps_hi += s[nt][2] + s[nt][3];
        }
        #pragma unroll
        for (int off = 1; off < 4; off <<= 1) {
            ps_lo += __shfl_xor_sync(0xffffffffu, ps_lo, off);
            ps_hi += __shfl_xor_sync(0xffffffffu, ps_hi, off);
        }
        l_lo = l_lo * al_lo + ps_lo;
        l_hi = l_hi * al_hi + ps_hi;
        m_lo = mn_lo; m_hi = mn_hi;
        #pragma unroll
        for (int nt = 0; nt < 8; nt++) {
            o[nt][0] *= al_lo; o[nt][1] *= al_lo;
            o[nt][2] *= al_hi; o[nt][3] *= al_hi;
        }

        // ---- write P (tf32) to sP[q][key]
        #pragma unroll
        for (int nt = 0; nt < 8; nt++) {
            int kc = nt * 8 + 2 * tg;
            float2 p0 = make_float2(to_tf32(s[nt][0]), to_tf32(s[nt][1]));
            float2 p1 = make_float2(to_tf32(s[nt][2]), to_tf32(s[nt][3]));
            *(float2*)&sP[(wq + gid) * AT_STR + kc]     = p0;
            *(float2*)&sP[(wq + gid + 8) * AT_STR + kc] = p1;
        }
        __syncthreads();

        // ---- O += P @ V
        #pragma unroll
        for (int ks = 0; ks < 8; ks++) {
            uint32_t pa[4], bf[8][2];
            int r0 = (wq + gid) * AT_STR, r1 = (wq + gid + 8) * AT_STR;
            pa[0] = __float_as_uint(sP[r0 + ks * 8 + tg]);
            pa[1] = __float_as_uint(sP[r1 + ks * 8 + tg]);
            pa[2] = __float_as_uint(sP[r0 + ks * 8 + tg + 4]);
            pa[3] = __float_as_uint(sP[r1 + ks * 8 + tg + 4]);
            int vr0 = (ks * 8 + tg) * AT_STR;
            int vr1 = (ks * 8 + tg + 4) * AT_STR;
            #pragma unroll
            for (int nt = 0; nt < 8; nt++) {
                int cc = nt * 8 + gid;
                bf[nt][0] = __float_as_uint(sV[vr0 + cc]);
                bf[nt][1] = __float_as_uint(sV[vr1 + cc]);
            }
            #pragma unroll
            for (int nt = 0; nt < 8; nt++)
                mma_tf32(o[nt], pa[0], pa[1], pa[2], pa[3], bf[nt][0], bf[nt][1]);
        }
        __syncthreads();   // protect sP/sV before next iteration's loads
    }

    // ---- epilogue: normalize and store
    float inv_lo = 1.0f / l_lo;
    float inv_hi = 1.0f / l_hi;
    #pragma unroll
    for (int nt = 0; nt < 8; nt++) {
        int d = nt * 8 + 2 * tg;
        size_t r0 = base + (size_t)(q0 + wq + gid) * DM + d;
        size_t r1 = base + (size_t)(q0 + wq + gid + 8) * DM + d;
        *(float2*)(O + r0) = make_float2(o[nt][0] * inv_lo, o[nt][1] * inv_lo);
        *(float2*)(O + r1) = make_float2(o[nt][2] * inv_hi, o[nt][3] * inv_hi);
    }
}

// ---------------- launcher -------------------------------------------------
extern "C" void kernel_launch(void* const* d_in, const int* in_sizes, int n_in,
                              void* d_out, int out_size)
{
    const float* x      = (const float*)d_in[0];
    const float* Wq     = (const float*)d_in[1];
    const float* bq     = (const float*)d_in[2];
    const float* Wk     = (const float*)d_in[3];
    const float* bk     = (const float*)d_in[4];
    const float* Wv     = (const float*)d_in[5];
    const float* bv     = (const float*)d_in[6];
    const float* Wo     = (const float*)d_in[7];
    const float* bo     = (const float*)d_in[8];
    const float* alpha1 = (const float*)d_in[9];
    const float* beta1  = (const float*)d_in[10];
    const float* alpha2 = (const float*)d_in[11];
    const float* beta2  = (const float*)d_in[12];
    const float* W1     = (const float*)d_in[13];
    const float* b1     = (const float*)d_in[14];
    const float* W2     = (const float*)d_in[15];
    const float* b2     = (const float*)d_in[16];
    float* out = (float*)d_out;

    float *xn, *q, *k, *v, *ao, *x2, *hn, *h1;
    cudaGetSymbolAddress((void**)&xn, g_xn);
    cudaGetSymbolAddress((void**)&q,  g_q);
    cudaGetSymbolAddress((void**)&k,  g_k);
    cudaGetSymbolAddress((void**)&v,  g_v);
    cudaGetSymbolAddress((void**)&ao, g_ao);
    cudaGetSymbolAddress((void**)&x2, g_x2);
    cudaGetSymbolAddress((void**)&hn, g_hn);
    cudaGetSymbolAddress((void**)&h1, g_h1);

    // 1. x_n = norm1(x)
    norm_kernel<<<ROWS, 256>>>(x, alpha1, beta1, xn);

    // 2. Q/K/V projections
    dim3 gqkv(DM / 128, ROWS / 128);   // (8, 32)
    tgemm<false, false><<<gqkv, 256>>>(xn, Wq, bq, nullptr, q, ROWS, DM, DM);
    tgemm<false, false><<<gqkv, 256>>>(xn, Wk, bk, nullptr, k, ROWS, DM, DM);
    tgemm<false, false><<<gqkv, 256>>>(xn, Wv, bv, nullptr, v, ROWS, DM, DM);

    // 3. attention
    int att_smem = 3 * 64 * AT_STR * (int)sizeof(float);   // 55296 B
    cudaFuncSetAttribute(attn_mma_kernel, cudaFuncAttributeMaxDynamicSharedMemorySize, att_smem);
    attn_mma_kernel<<<dim3(SEQ / 64, BATCH * NH), 128, att_smem>>>(q, k, v, ao);

    // 4. x2 = x_n + ao@Wo + bo
    tgemm<false, true><<<gqkv, 256>>>(ao, Wo, bo, xn, x2, ROWS, DM, DM);

    // 5. h_n = norm2(x2)
    norm_kernel<<<ROWS, 256>>>(x2, alpha2, beta2, hn);

    // 6. h1 = relu(h_n@W1 + b1)
    tgemm<true, false><<<dim3(DFF / 128, ROWS / 128), 256>>>(hn, W1, b1, nullptr, h1, ROWS, DFF, DM);

    // 7. out = x2 + h1@W2 + b2
    tgemm<false, true><<<dim3(DM / 128, ROWS / 128), 256>>>(h1, W2, b2, x2, out, ROWS, DM, DFF);
}